// round 16
// baseline (speedup 1.0000x reference)
#include <cuda_runtime.h>
#include <cuda_bf16.h>
#include <cstdint>

// Problem constants (fixed by the dataset)
static constexpr int NN  = 100000;   // nodes
static constexpr int NE  = 600000;   // edges
static constexpr int NBLK = (NN + 1023) / 1024;  // 98 scan blocks

// ---------------- scratch (device globals: no allocations allowed) ----------
__device__ int   g_src[NE];
__device__ int   g_dst[NE];
__device__ int   g_cnt[NN];      // in-degree (excl self)
__device__ int   g_rowptr[NN];   // CSR row starts
__device__ int   g_fill[NN];     // scatter fill counters
__device__ int   g_bsum[NBLK];
__device__ int   g_boff[NBLK];
__device__ float g_dinv[NN];
__device__ int   g_csrc[NE];     // CSR-sorted source ids
__device__ float g_cnorm[NE];    // CSR-sorted edge norms
__device__ float g_h1[(size_t)NN * 128];   // x @ W1 (raw)
__device__ float g_a1[(size_t)NN * 128];   // aggregated layer-1
__device__ float g_h2[(size_t)NN * 64];    // relu(a1+b1) @ W2 (raw)
__device__ __nv_bfloat16 g_w1h[128 * 128]; // [n][k] transposed, hi
__device__ __nv_bfloat16 g_w1l[128 * 128];
__device__ __nv_bfloat16 g_w2h[64 * 128];
__device__ __nv_bfloat16 g_w2l[64 * 128];

// ---------------- helpers ----------------------------------------------------
__device__ __forceinline__ uint32_t smem_to_u32(const void* p) {
    uint32_t a;
    asm("{ .reg .u64 t; cvta.to.shared.u64 t, %1; cvt.u32.u64 %0, t; }"
        : "=r"(a) : "l"(p));
    return a;
}
// XOR-swizzle a byte offset within a [rows][256B] tile (16B chunks x row%8)
__device__ __forceinline__ int swz(int o) { return o ^ ((o >> 4) & 0x70); }

__device__ __forceinline__ void ldm_x4(uint32_t* r, uint32_t addr) {
    asm volatile("ldmatrix.sync.aligned.m8n8.x4.shared.b16 {%0,%1,%2,%3}, [%4];"
                 : "=r"(r[0]), "=r"(r[1]), "=r"(r[2]), "=r"(r[3]) : "r"(addr));
}
__device__ __forceinline__ void ldm_x2(uint32_t* r, uint32_t addr) {
    asm volatile("ldmatrix.sync.aligned.m8n8.x2.shared.b16 {%0,%1}, [%2];"
                 : "=r"(r[0]), "=r"(r[1]) : "r"(addr));
}
__device__ __forceinline__ void mma_bf16(float* c, const uint32_t* a, const uint32_t* b) {
    asm volatile(
        "mma.sync.aligned.m16n8k16.row.col.f32.bf16.bf16.f32 "
        "{%0,%1,%2,%3}, {%4,%5,%6,%7}, {%8,%9}, {%0,%1,%2,%3};"
        : "+f"(c[0]), "+f"(c[1]), "+f"(c[2]), "+f"(c[3])
        : "r"(a[0]), "r"(a[1]), "r"(a[2]), "r"(a[3]), "r"(b[0]), "r"(b[1]));
}

__device__ __forceinline__ uint32_t pack_bf2(__nv_bfloat16 a, __nv_bfloat16 b) {
    __nv_bfloat162 t = __halves2bfloat162(a, b);
    return *reinterpret_cast<uint32_t*>(&t);
}
__device__ __forceinline__ void split1(float v, __nv_bfloat16& h, __nv_bfloat16& l) {
    h = __float2bfloat16(v);
    l = __float2bfloat16(v - __bfloat162float(h));
}

// ---------------- edge preprocessing -----------------------------------------
// convert + in-degree count, with per-block int64 detection (same 64 entries
// in every block -> same verdict everywhere)
__global__ void convert_count_kernel(const void* ei) {
    __shared__ int ok[2];
    __shared__ int sh_is64;
    const int* pi = (const int*)ei;
    int t = threadIdx.x;
    if (t < 64) {
        bool z = (pi[2 * t + 1] == 0);
        unsigned m = __ballot_sync(0xffffffffu, z);
        if ((t & 31) == 0) ok[t >> 5] = (m == 0xffffffffu) ? 1 : 0;
    }
    __syncthreads();
    if (t == 0) sh_is64 = ok[0] & ok[1];
    __syncthreads();
    int is64 = sh_is64;

    int e = blockIdx.x * blockDim.x + t;
    if (e >= NE) return;
    int s, d;
    if (is64) {
        const long long* p = (const long long*)ei;
        s = (int)p[e];
        d = (int)p[e + NE];
    } else {
        s = pi[e];
        d = pi[e + NE];
    }
    g_src[e] = s;
    g_dst[e] = d;
    atomicAdd(&g_cnt[d], 1);
}

// ---------------- CSR build: warp-scan + scatter ------------------------------
__global__ void scan1_kernel() {  // grid NBLK, block 1024
    __shared__ int warpsum[32];
    int b = blockIdx.x, t = threadIdx.x;
    int i = b * 1024 + t;
    int lane = t & 31, w = t >> 5;
    int v = (i < NN) ? g_cnt[i] : 0;
    int x = v;
    #pragma unroll
    for (int off = 1; off < 32; off <<= 1) {
        int y = __shfl_up_sync(0xffffffffu, x, off);
        if (lane >= off) x += y;
    }
    if (lane == 31) warpsum[w] = x;
    __syncthreads();
    if (w == 0) {
        int s = warpsum[lane];
        #pragma unroll
        for (int off = 1; off < 32; off <<= 1) {
            int y = __shfl_up_sync(0xffffffffu, s, off);
            if (lane >= off) s += y;
        }
        warpsum[lane] = s;
    }
    __syncthreads();
    int base = (w > 0) ? warpsum[w - 1] : 0;
    int incl = base + x;
    if (i < NN) g_rowptr[i] = incl - v;   // exclusive within block
    if (t == 1023) g_bsum[b] = incl;
}

__global__ void scan2_kernel() {  // 1 block, 128 threads (NBLK <= 128)
    __shared__ int ws[4];
    int t = threadIdx.x, lane = t & 31, w = t >> 5;
    int v = (t < NBLK) ? g_bsum[t] : 0;
    int x = v;
    #pragma unroll
    for (int off = 1; off < 32; off <<= 1) {
        int y = __shfl_up_sync(0xffffffffu, x, off);
        if (lane >= off) x += y;
    }
    if (lane == 31) ws[w] = x;
    __syncthreads();
    if (t == 0) {
        int run = 0;
        #pragma unroll
        for (int j = 0; j < 4; j++) { int z = ws[j]; ws[j] = run; run += z; }
    }
    __syncthreads();
    if (t < NBLK) g_boff[t] = ws[w] + x - v;   // exclusive
}

// rowptr finalize + dinv + fill-zero fused (same [NN] sweep)
__global__ void scan3_kernel() {
    int i = blockIdx.x * blockDim.x + threadIdx.x;
    if (i < NN) {
        g_rowptr[i] += g_boff[i >> 10];
        g_dinv[i] = rsqrtf((float)g_cnt[i] + 1.0f);
        g_fill[i] = 0;
    }
}

__global__ void scatter_kernel() {
    int e = blockIdx.x * blockDim.x + threadIdx.x;
    if (e >= NE) return;
    int s = g_src[e], d = g_dst[e];
    int pos = g_rowptr[d] + atomicAdd(&g_fill[d], 1);
    g_csrc[pos] = s;
    g_cnorm[pos] = g_dinv[s] * g_dinv[d];
}

// both weight matrices: transpose + hi/lo split in one launch
__global__ void wconv_all_kernel(const float* __restrict__ W1,
                                 const float* __restrict__ W2) {
    int i = blockIdx.x * blockDim.x + threadIdx.x;
    if (i < 128 * 128) {
        int k = i >> 7, n = i & 127;   // W1 [k][n], Ncols=128
        __nv_bfloat16 h, l;
        split1(W1[i], h, l);
        g_w1h[n * 128 + k] = h;
        g_w1l[n * 128 + k] = l;
    } else if (i < 128 * 128 + 128 * 64) {
        int j = i - 128 * 128;
        int k = j >> 6, n = j & 63;    // W2 [k][n], Ncols=64
        __nv_bfloat16 h, l;
        split1(W2[j], h, l);
        g_w2h[n * 128 + k] = h;
        g_w2l[n * 128 + k] = l;
    }
}

// ---------------- HMMA GEMM with in-kernel hi/lo split -----------------------
// C[M,NDIM] = op(A)[M,128] @ W[128,NDIM];  op(A) = relu(A + abias) when RELU.
// 3 passes: Ah*Bh + Ah*Bl + Al*Bh, fp32 accum. Epilogue: raw C only.
template <int NDIM, bool RELU>
__global__ void __launch_bounds__(256)
mma_gemm(const float* __restrict__ A, const float* __restrict__ abias,
         const __nv_bfloat16* __restrict__ Bh, const __nv_bfloat16* __restrict__ Bl,
         float* __restrict__ C, int M) {
    extern __shared__ char smem[];
    constexpr int WARP_N = NDIM / 2;   // 64 or 32
    constexpr int NT_N = WARP_N / 8;   // 8 or 4
    constexpr int A_BYTES = 128 * 256;
    constexpr int B_BYTES = NDIM * 256;

    const uint32_t sAh = smem_to_u32(smem);
    const uint32_t sAl = sAh + A_BYTES;
    const uint32_t sB0 = sAl + A_BYTES;
    const uint32_t sB1 = sB0 + B_BYTES;

    const int tid = threadIdx.x, wid = tid >> 5, lane = tid & 31;
    const int warp_row = wid & 3, warp_col = wid >> 2;
    const int rowBase = blockIdx.x * 128;
    const int vr = (M - rowBase < 128) ? (M - rowBase) : 128;

    // ---- A loader: fp32 -> bf16 hi/lo, swizzled SMEM
    {
        const float* gA = A + (size_t)rowBase * 128;
        for (int idx = tid; idx < 128 * 16; idx += 256) {
            int row = idx >> 4, c = idx & 15;
            float4 v0 = make_float4(0.f, 0.f, 0.f, 0.f);
            float4 v1 = v0;
            if (row < vr) {
                v0 = *(const float4*)(gA + (size_t)row * 128 + c * 8);
                v1 = *(const float4*)(gA + (size_t)row * 128 + c * 8 + 4);
            }
            if (RELU) {
                float4 b0 = *(const float4*)(abias + c * 8);
                float4 b1 = *(const float4*)(abias + c * 8 + 4);
                v0.x = fmaxf(v0.x + b0.x, 0.f); v0.y = fmaxf(v0.y + b0.y, 0.f);
                v0.z = fmaxf(v0.z + b0.z, 0.f); v0.w = fmaxf(v0.w + b0.w, 0.f);
                v1.x = fmaxf(v1.x + b1.x, 0.f); v1.y = fmaxf(v1.y + b1.y, 0.f);
                v1.z = fmaxf(v1.z + b1.z, 0.f); v1.w = fmaxf(v1.w + b1.w, 0.f);
            }
            __nv_bfloat16 h[8], l[8];
            split1(v0.x, h[0], l[0]); split1(v0.y, h[1], l[1]);
            split1(v0.z, h[2], l[2]); split1(v0.w, h[3], l[3]);
            split1(v1.x, h[4], l[4]); split1(v1.y, h[5], l[5]);
            split1(v1.z, h[6], l[6]); split1(v1.w, h[7], l[7]);
            int o = swz(row * 256 + c * 16);
            *(uint4*)(smem + o) = make_uint4(
                pack_bf2(h[0], h[1]), pack_bf2(h[2], h[3]),
                pack_bf2(h[4], h[5]), pack_bf2(h[6], h[7]));
            *(uint4*)(smem + A_BYTES + o) = make_uint4(
                pack_bf2(l[0], l[1]), pack_bf2(l[2], l[3]),
                pack_bf2(l[4], l[5]), pack_bf2(l[6], l[7]));
        }
    }
    // ---- B loader
    {
        for (int idx = tid; idx < NDIM * 16; idx += 256) {
            int row = idx >> 4, c = idx & 15;
            int o = swz(row * 256 + c * 16);
            *(uint4*)(smem + 2 * A_BYTES + o) =
                *(const uint4*)(Bh + (size_t)row * 128 + c * 8);
            *(uint4*)(smem + 2 * A_BYTES + B_BYTES + o) =
                *(const uint4*)(Bl + (size_t)row * 128 + c * 8);
        }
    }
    __syncthreads();

    float acc[2][NT_N][4];
    #pragma unroll
    for (int i = 0; i < 2; i++)
        #pragma unroll
        for (int j = 0; j < NT_N; j++)
            #pragma unroll
            for (int q = 0; q < 4; q++) acc[i][j][q] = 0.0f;

    const int at = lane >> 3;
    const int ar = lane & 7;
    const int aRow0 = warp_row * 32 + ar + (at & 1) * 8;
    const int aKt = (at >> 1) * 8;
    const int l15 = lane & 15;
    const int bt = l15 >> 3, br = l15 & 7;
    const int bN0 = warp_col * WARP_N + br;
    const int bKt = bt * 8;

    auto run_pass = [&](uint32_t aBase, uint32_t bBase) {
        #pragma unroll
        for (int ks = 0; ks < 8; ks++) {
            uint32_t a[2][4];
            #pragma unroll
            for (int mi = 0; mi < 2; mi++) {
                int row = aRow0 + mi * 16;
                ldm_x4(a[mi], aBase + swz(row * 256 + (ks * 16 + aKt) * 2));
            }
            uint32_t b[NT_N][2];
            #pragma unroll
            for (int ni = 0; ni < NT_N; ni++) {
                int n = bN0 + ni * 8;
                ldm_x2(b[ni], bBase + swz(n * 256 + (ks * 16 + bKt) * 2));
            }
            #pragma unroll
            for (int mi = 0; mi < 2; mi++)
                #pragma unroll
                for (int ni = 0; ni < NT_N; ni++)
                    mma_bf16(acc[mi][ni], a[mi], b[ni]);
        }
    };

    run_pass(sAh, sB0);   // Ah * Bh
    run_pass(sAh, sB1);   // Ah * Bl
    run_pass(sAl, sB0);   // Al * Bh

    // ---- epilogue: raw C only
    const int erow0 = rowBase + warp_row * 32 + (lane >> 2);
    const int ecol0 = warp_col * WARP_N + (lane & 3) * 2;
    #pragma unroll
    for (int mi = 0; mi < 2; mi++) {
        #pragma unroll
        for (int p = 0; p < 2; p++) {
            int row = erow0 + mi * 16 + p * 8;
            if (row >= M) continue;
            #pragma unroll
            for (int ni = 0; ni < NT_N; ni++) {
                int col = ecol0 + ni * 8;
                *(float2*)(C + (size_t)row * NDIM + col) =
                    make_float2(acc[mi][ni][2 * p], acc[mi][ni][2 * p + 1]);
            }
        }
    }
}

// ---------------- CSR aggregation: shfl-broadcast gather ---------------------
// warp per node, 128 features. Edge indices/norms loaded coalesced once per
// 32-edge chunk; inner loop uses shfl (no memory dependency) so all gathers
// pipeline.
__global__ void agg_csr128(const float* __restrict__ h, float* __restrict__ out) {
    int t = blockIdx.x * blockDim.x + threadIdx.x;
    int n = t >> 5;
    int lane = t & 31;
    if (n >= NN) return;
    float dv = g_dinv[n];
    float w = dv * dv;
    const float4* hv = (const float4*)h;
    float4 acc = hv[(size_t)n * 32 + lane];
    acc.x *= w; acc.y *= w; acc.z *= w; acc.w *= w;
    int p = g_rowptr[n];
    int deg = g_cnt[n];
    for (int base = 0; base < deg; base += 32) {
        int cnt = min(32, deg - base);
        int idx = 0;
        float nm = 0.f;
        if (lane < cnt) {
            idx = __ldg(&g_csrc[p + base + lane]);
            nm = __ldg(&g_cnorm[p + base + lane]);
        }
        for (int j = 0; j < cnt; j++) {
            int s = __shfl_sync(0xffffffffu, idx, j);
            float nj = __shfl_sync(0xffffffffu, nm, j);
            float4 v = hv[(size_t)s * 32 + lane];
            acc.x += v.x * nj; acc.y += v.y * nj;
            acc.z += v.z * nj; acc.w += v.w * nj;
        }
    }
    ((float4*)out)[(size_t)n * 32 + lane] = acc;
}

// half-warp per node, 64 features; adds bias. shfl within 16-wide segments.
__global__ void agg_csr64(const float* __restrict__ h,
                          const float* __restrict__ bias,
                          float* __restrict__ out) {
    int t = blockIdx.x * blockDim.x + threadIdx.x;
    int n = t >> 4;
    int lane = t & 15;
    if (n >= NN) return;
    unsigned hmask = 0xFFFFu << ((threadIdx.x & 16));  // own half's mask
    float dv = g_dinv[n];
    float w = dv * dv;
    const float4* hv = (const float4*)h;
    float4 bb = ((const float4*)bias)[lane];
    float4 acc = hv[(size_t)n * 16 + lane];
    acc.x = acc.x * w + bb.x; acc.y = acc.y * w + bb.y;
    acc.z = acc.z * w + bb.z; acc.w = acc.w * w + bb.w;
    int p = g_rowptr[n];
    int deg = g_cnt[n];
    for (int base = 0; base < deg; base += 16) {
        int cnt = min(16, deg - base);
        int idx = 0;
        float nm = 0.f;
        if (lane < cnt) {
            idx = __ldg(&g_csrc[p + base + lane]);
            nm = __ldg(&g_cnorm[p + base + lane]);
        }
        for (int j = 0; j < cnt; j++) {
            int s = __shfl_sync(hmask, idx, j, 16);
            float nj = __shfl_sync(hmask, nm, j, 16);
            float4 v = hv[(size_t)s * 16 + lane];
            acc.x += v.x * nj; acc.y += v.y * nj;
            acc.z += v.z * nj; acc.w += v.w * nj;
        }
    }
    ((float4*)out)[(size_t)n * 16 + lane] = acc;
}

// ---------------- launcher ---------------------------------------------------
extern "C" void kernel_launch(void* const* d_in, const int* in_sizes, int n_in,
                              void* d_out, int out_size) {
    const float* x  = (const float*)d_in[0];
    const void*  ei = d_in[1];
    const float* W1 = (const float*)d_in[2];
    const float* b1 = (const float*)d_in[3];
    const float* W2 = (const float*)d_in[4];
    const float* b2 = (const float*)d_in[5];
    float* out = (float*)d_out;

    float *h1, *a1, *h2;
    int *cntp;
    cudaGetSymbolAddress((void**)&h1, g_h1);
    cudaGetSymbolAddress((void**)&a1, g_a1);
    cudaGetSymbolAddress((void**)&h2, g_h2);
    cudaGetSymbolAddress((void**)&cntp, g_cnt);
    __nv_bfloat16 *w1h, *w1l, *w2h, *w2l;
    cudaGetSymbolAddress((void**)&w1h, g_w1h);
    cudaGetSymbolAddress((void**)&w1l, g_w1l);
    cudaGetSymbolAddress((void**)&w2h, g_w2h);
    cudaGetSymbolAddress((void**)&w2l, g_w2l);

    constexpr int SMEM1 = 2 * 128 * 256 + 2 * 128 * 256;  // 131072
    constexpr int SMEM2 = 2 * 128 * 256 + 2 * 64 * 256;   // 98304
    cudaFuncSetAttribute(mma_gemm<128, false>,
                         cudaFuncAttributeMaxDynamicSharedMemorySize, SMEM1);
    cudaFuncSetAttribute(mma_gemm<64, true>,
                         cudaFuncAttributeMaxDynamicSharedMemorySize, SMEM2);

    const int T = 256;
    // 1. edge preprocessing + CSR build
    cudaMemsetAsync(cntp, 0, NN * sizeof(int));
    convert_count_kernel<<<(NE + T - 1) / T, T>>>(ei);
    scan1_kernel<<<NBLK, 1024>>>();
    scan2_kernel<<<1, 128>>>();
    scan3_kernel<<<(NN + T - 1) / T, T>>>();
    scatter_kernel<<<(NE + T - 1) / T, T>>>();

    // 2. weight splits (single tiny launch)
    wconv_all_kernel<<<(128 * 128 + 128 * 64 + T - 1) / T, T>>>(W1, W2);

    // 3. layer 1: h1 = x @ W1; CSR aggregate (self + edges) -> a1
    const int GRID = (NN + 127) / 128;  // 782
    mma_gemm<128, false><<<GRID, 256, SMEM1>>>(x, nullptr, w1h, w1l, h1, NN);
    agg_csr128<<<(NN * 32 + T - 1) / T, T>>>(h1, a1);

    // 4. layer 2: h2 = relu(a1+b1) @ W2; CSR aggregate + b2 -> out
    mma_gemm<64, true><<<GRID, 256, SMEM2>>>(a1, b1, w2h, w2l, h2, NN);
    agg_csr64<<<(NN * 16 + T - 1) / T, T>>>(h2, b2, out);
}